// round 4
// baseline (speedup 1.0000x reference)
#include <cuda_runtime.h>
#include <math.h>
#include <stdint.h>

// Problem constants
#define HEI   256
#define WID   256
#define HW    65536
#define CIN   192
#define C3    576
#define NB    4
#define NHEADS 8
#define HDIM  24

// ---------------- device scratch ----------------
__device__ __align__(256) float g_qkv [(size_t)NB * C3 * HW];
__device__ __align__(256) float g_qkvd[(size_t)NB * C3 * HW];
__device__ __align__(256) float g_gram[NB * NHEADS * HDIM * HDIM];
__device__ __align__(256) float g_sums[NB * 2 * CIN];
__device__ __align__(256) float g_M   [NB * CIN * CIN];

__device__ __forceinline__ uint32_t to_tf32_bits(float x) {
    uint32_t y; asm("cvt.rna.tf32.f32 %0, %1;" : "=r"(y) : "f"(x)); return y;
}

__device__ __forceinline__ void mma_tf32_16x8x8(
    float& c0, float& c1, float& c2, float& c3,
    uint32_t a0, uint32_t a1, uint32_t a2, uint32_t a3,
    uint32_t b0, uint32_t b1)
{
    asm volatile(
        "mma.sync.aligned.m16n8k8.row.col.f32.tf32.tf32.f32 "
        "{%0,%1,%2,%3}, {%4,%5,%6,%7}, {%8,%9}, {%0,%1,%2,%3};"
        : "+f"(c0), "+f"(c1), "+f"(c2), "+f"(c3)
        : "r"(a0), "r"(a1), "r"(a2), "r"(a3), "r"(b0), "r"(b1));
}

// ---------------- zero small accumulators ----------------
__global__ void zero_small_kernel() {
    int i = blockIdx.x * 256 + threadIdx.x;
    if (i < NB * NHEADS * HDIM * HDIM) g_gram[i] = 0.0f;
    if (i < NB * 2 * CIN)              g_sums[i] = 0.0f;
}

// ---------------- tf32 mma.sync GEMM ----------------
// C[M=channels, N=pixels] = A[M,K] @ B[K,N], K=192.
// Block: BM=192, BN=128, BK=32, 256 thr = 8 warps (4M x 2N), warp tile 48x64.
// Grid: (channel tiles, pixel tiles, batch) -- channel tiles fastest so the 3
// blocks sharing one x pixel-slice run concurrently and hit L2.
#define BM 192
#define BN 128
#define BK 32
#define AS_STRIDE 36
#define BS_STRIDE 136
#define AS_FLOATS (BM * AS_STRIDE)
#define BS_FLOATS (BK * BS_STRIDE)
#define STAGE_FLOATS (AS_FLOATS + BS_FLOATS)
#define GEMM_SMEM_BYTES (2 * STAGE_FLOATS * 4)   // 90112

template <int MODE>
__global__ void __launch_bounds__(256) gemm_mma_kernel(
    const float* __restrict__ xin, const float* __restrict__ win, float* __restrict__ outp)
{
    extern __shared__ float smem[];
    const int tid  = threadIdx.x;
    const int b    = blockIdx.z;
    const int pix0 = blockIdx.y * BN;

    const float* Ag; const float* Bg; float* Cg;
    if (MODE == 0) {
        const int m0 = blockIdx.x * BM;
        Ag = win + (size_t)m0 * CIN;
        Bg = xin + (size_t)b * CIN * HW;
        Cg = g_qkv + ((size_t)b * C3 + m0) * HW;
    } else {
        Ag = g_M + (size_t)b * CIN * CIN;
        Bg = g_qkvd + ((size_t)b * C3 + 2 * CIN) * HW;
        Cg = outp + (size_t)b * CIN * HW;
    }

    const int warp  = tid >> 5;
    const int lane  = tid & 31;
    const int warpM = warp >> 1;
    const int warpN = warp & 1;
    const int m0w   = warpM * 48;
    const int n0w   = warpN * 64;
    const int g     = lane >> 2;
    const int cq    = lane & 3;

    const int a_row = tid >> 3;
    const int a_kq  = (tid & 7) * 4;
    const int b_kr  = tid >> 5;
    const int b_n4  = lane * 4;

    float4 areg[6], breg[4];

    auto loadA = [&](int t) {
#pragma unroll
        for (int i = 0; i < 6; i++)
            areg[i] = *(const float4*)&Ag[(size_t)(a_row + i * 32) * CIN + t * BK + a_kq];
    };
    auto loadB = [&](int t) {
#pragma unroll
        for (int i = 0; i < 4; i++)
            breg[i] = *(const float4*)&Bg[(size_t)(t * BK + b_kr + i * 8) * HW + pix0 + b_n4];
    };
    auto storeA = [&](int s) {
        float* As = smem + s * STAGE_FLOATS;
#pragma unroll
        for (int i = 0; i < 6; i++) {
            uint32_t* p = (uint32_t*)&As[(a_row + i * 32) * AS_STRIDE + a_kq];
            p[0] = to_tf32_bits(areg[i].x); p[1] = to_tf32_bits(areg[i].y);
            p[2] = to_tf32_bits(areg[i].z); p[3] = to_tf32_bits(areg[i].w);
        }
    };
    auto storeB = [&](int s) {
        float* Bs = smem + s * STAGE_FLOATS + AS_FLOATS;
#pragma unroll
        for (int i = 0; i < 4; i++) {
            uint32_t* p = (uint32_t*)&Bs[(b_kr + i * 8) * BS_STRIDE + b_n4];
            p[0] = to_tf32_bits(breg[i].x); p[1] = to_tf32_bits(breg[i].y);
            p[2] = to_tf32_bits(breg[i].z); p[3] = to_tf32_bits(breg[i].w);
        }
    };

    float c[3][8][4];
#pragma unroll
    for (int i = 0; i < 3; i++)
#pragma unroll
        for (int j = 0; j < 8; j++)
#pragma unroll
            for (int q = 0; q < 4; q++) c[i][j][q] = 0.0f;

    loadA(0); loadB(0);
    storeA(0); storeB(0);
    __syncthreads();

#pragma unroll 1
    for (int t = 0; t < 6; t++) {
        if (t < 5) { loadA(t + 1); loadB(t + 1); }
        const int s = t & 1;
        const uint32_t* As = (const uint32_t*)(smem + s * STAGE_FLOATS);
        const uint32_t* Bs = (const uint32_t*)(smem + s * STAGE_FLOATS + AS_FLOATS);
#pragma unroll
        for (int kk = 0; kk < 4; kk++) {
            const int kb = kk * 8;
            uint32_t af[3][4], bf[8][2];
#pragma unroll
            for (int ms = 0; ms < 3; ms++) {
                const int mrow = m0w + ms * 16 + g;
                af[ms][0] = As[(mrow)     * AS_STRIDE + kb + cq];
                af[ms][1] = As[(mrow + 8) * AS_STRIDE + kb + cq];
                af[ms][2] = As[(mrow)     * AS_STRIDE + kb + cq + 4];
                af[ms][3] = As[(mrow + 8) * AS_STRIDE + kb + cq + 4];
            }
#pragma unroll
            for (int ns = 0; ns < 8; ns++) {
                const int ncol = n0w + ns * 8 + g;
                bf[ns][0] = Bs[(kb + cq)     * BS_STRIDE + ncol];
                bf[ns][1] = Bs[(kb + cq + 4) * BS_STRIDE + ncol];
            }
#pragma unroll
            for (int ms = 0; ms < 3; ms++)
#pragma unroll
                for (int ns = 0; ns < 8; ns++)
                    mma_tf32_16x8x8(c[ms][ns][0], c[ms][ns][1], c[ms][ns][2], c[ms][ns][3],
                                    af[ms][0], af[ms][1], af[ms][2], af[ms][3],
                                    bf[ns][0], bf[ns][1]);
        }
        if (t < 5) {
            storeA((t + 1) & 1); storeB((t + 1) & 1);
            __syncthreads();
        }
    }

#pragma unroll
    for (int ms = 0; ms < 3; ms++) {
        const int m = m0w + ms * 16 + g;
#pragma unroll
        for (int ns = 0; ns < 8; ns++) {
            const int n = pix0 + n0w + ns * 8 + cq * 2;
            *(float2*)&Cg[(size_t)m * HW + n]       = make_float2(c[ms][ns][0], c[ms][ns][1]);
            *(float2*)&Cg[(size_t)(m + 8) * HW + n] = make_float2(c[ms][ns][2], c[ms][ns][3]);
        }
    }
}

// ---------------- depthwise 3x3 + fused per-channel sumsq ----------------
__global__ void __launch_bounds__(256) dwconv3x3_kernel(const float* __restrict__ w)
{
    const int bc = blockIdx.x;
    const int ch = bc % C3;
    const int b  = bc / C3;
    const float* ip = g_qkv  + (size_t)bc * HW;
    float*       op = g_qkvd + (size_t)bc * HW;

    __shared__ float s[34][258];
    const int tid = threadIdx.x;
    const int y0  = blockIdx.y * 32;

    for (int i = tid; i < 34 * 256; i += 256) {
        const int r = i >> 8, xc = i & 255;
        const int y = y0 + r - 1;
        s[r][xc + 1] = (y >= 0 && y < HEI) ? ip[y * WID + xc] : 0.0f;
    }
    if (tid < 34) { s[tid][0] = 0.0f; s[tid][257] = 0.0f; }

    float wr[9];
#pragma unroll
    for (int i = 0; i < 9; i++) wr[i] = w[ch * 9 + i];
    __syncthreads();

    float ssq = 0.0f;
#pragma unroll 4
    for (int r = 0; r < 32; r++) {
        float acc = 0.0f;
#pragma unroll
        for (int dy = 0; dy < 3; dy++)
#pragma unroll
            for (int dx = 0; dx < 3; dx++)
                acc = fmaf(s[r + dy][tid + dx], wr[dy * 3 + dx], acc);
        op[(y0 + r) * WID + tid] = acc;
        ssq = fmaf(acc, acc, ssq);
    }

    if (ch < 2 * CIN) {
        __shared__ float red[8];
        const int lane = tid & 31, wp = tid >> 5;
#pragma unroll
        for (int o = 16; o; o >>= 1) ssq += __shfl_down_sync(0xffffffffu, ssq, o);
        if (lane == 0) red[wp] = ssq;
        __syncthreads();
        if (tid == 0) {
            float t = 0.0f;
#pragma unroll
            for (int i = 0; i < 8; i++) t += red[i];
            atomicAdd(&g_sums[b * 2 * CIN + ch], t);
        }
    }
}

// ---------------- tensor-core gram with 3xTF32 ----------------
// G[b,h,:,:] (24x24) += q[24, px] @ k[24, px]^T over this block's pixel chunk.
// Each byte of q/k is read from DRAM exactly once across the whole grid.
#define GP      32          // pixel chunks per (b,h)
#define GPX     (HW / GP)   // 2048 pixels per block
#define GSUB    256         // pixels per SMEM subtile
#define QS_ROWS 32          // padded to 32 rows (rows 24-31 zero)
#define GS_STRIDE 260       // floats; 260 % 32 == 4 -> conflict-free frag LDS
#define GQ_FLOATS (QS_ROWS * GS_STRIDE)
#define GK_FLOATS (HDIM * GS_STRIDE)
#define GRED_FLOATS (8 * HDIM * HDIM)
#define GRAM_SMEM_BYTES ((GQ_FLOATS + GK_FLOATS + GRED_FLOATS) * 4)

__global__ void __launch_bounds__(256) gram_tc_kernel()
{
    extern __shared__ float sm[];
    float* qs  = sm;                       // [32][260]
    float* ks  = sm + GQ_FLOATS;           // [24][260]
    float* red = sm + GQ_FLOATS + GK_FLOATS; // [8][576]

    const int bh = blockIdx.y;
    const int b = bh >> 3, h = bh & 7;
    const int px_base = blockIdx.x * GPX;
    const float* qb = g_qkvd + ((size_t)b * C3 + h * HDIM) * HW;
    const float* kb = qb + (size_t)CIN * HW;

    const int tid  = threadIdx.x;
    const int warp = tid >> 5;
    const int lane = tid & 31;
    const int g    = lane >> 2;
    const int cq   = lane & 3;

    // zero pad rows 24..31 of qs (read by 2nd M-tile; results discarded but keep clean)
    for (int i = tid; i < 8 * GS_STRIDE; i += 256) qs[HDIM * 0 + (24) * GS_STRIDE + i] = 0.0f;

    float c[2][3][4];
#pragma unroll
    for (int mt = 0; mt < 2; mt++)
#pragma unroll
        for (int nt = 0; nt < 3; nt++)
#pragma unroll
            for (int q = 0; q < 4; q++) c[mt][nt][q] = 0.0f;

#pragma unroll 1
    for (int it = 0; it < GPX / GSUB; it++) {
        const int px0 = px_base + it * GSUB;
        __syncthreads();
        // coalesced load: 24 rows x 64 float4 each for q and k
        for (int i = tid; i < HDIM * (GSUB / 4); i += 256) {
            const int row = i >> 6, c4 = i & 63;
            *(float4*)&qs[row * GS_STRIDE + c4 * 4] = *(const float4*)&qb[(size_t)row * HW + px0 + c4 * 4];
            *(float4*)&ks[row * GS_STRIDE + c4 * 4] = *(const float4*)&kb[(size_t)row * HW + px0 + c4 * 4];
        }
        __syncthreads();

        // warp handles pixel window [warp*32, warp*32+32): 4 k8 steps
#pragma unroll
        for (int k8 = 0; k8 < 4; k8++) {
            const int kb8 = warp * 32 + k8 * 8;
            uint32_t ah[2][4], al[2][4], bh2[3][2], bl[3][2];
#pragma unroll
            for (int mt = 0; mt < 2; mt++) {
                const int r0 = mt * 16 + g;
#pragma unroll
                for (int q = 0; q < 4; q++) {
                    const int rr = r0 + (q & 1) * 8;
                    const int cc = kb8 + cq + (q >> 1) * 4;
                    const float v = qs[rr * GS_STRIDE + cc];
                    ah[mt][q] = to_tf32_bits(v);
                    al[mt][q] = to_tf32_bits(v - __uint_as_float(ah[mt][q]));
                }
            }
#pragma unroll
            for (int nt = 0; nt < 3; nt++) {
                const int er = nt * 8 + g;
#pragma unroll
                for (int q = 0; q < 2; q++) {
                    const float v = ks[er * GS_STRIDE + kb8 + cq + q * 4];
                    bh2[nt][q] = to_tf32_bits(v);
                    bl[nt][q]  = to_tf32_bits(v - __uint_as_float(bh2[nt][q]));
                }
            }
#pragma unroll
            for (int mt = 0; mt < 2; mt++)
#pragma unroll
                for (int nt = 0; nt < 3; nt++) {
                    mma_tf32_16x8x8(c[mt][nt][0], c[mt][nt][1], c[mt][nt][2], c[mt][nt][3],
                                    ah[mt][0], ah[mt][1], ah[mt][2], ah[mt][3],
                                    bh2[nt][0], bh2[nt][1]);
                    mma_tf32_16x8x8(c[mt][nt][0], c[mt][nt][1], c[mt][nt][2], c[mt][nt][3],
                                    ah[mt][0], ah[mt][1], ah[mt][2], ah[mt][3],
                                    bl[nt][0], bl[nt][1]);
                    mma_tf32_16x8x8(c[mt][nt][0], c[mt][nt][1], c[mt][nt][2], c[mt][nt][3],
                                    al[mt][0], al[mt][1], al[mt][2], al[mt][3],
                                    bh2[nt][0], bh2[nt][1]);
                }
        }
    }

    // reduce 8 warps' partial G and atomically add to g_gram
    __syncthreads();
    float* rw = red + warp * (HDIM * HDIM);
#pragma unroll
    for (int mt = 0; mt < 2; mt++) {
        const int d = mt * 16 + g;
#pragma unroll
        for (int nt = 0; nt < 3; nt++) {
            const int e = nt * 8 + cq * 2;
            rw[d * HDIM + e]     = c[mt][nt][0];
            rw[d * HDIM + e + 1] = c[mt][nt][1];
            if (d + 8 < HDIM) {
                rw[(d + 8) * HDIM + e]     = c[mt][nt][2];
                rw[(d + 8) * HDIM + e + 1] = c[mt][nt][3];
            }
        }
    }
    __syncthreads();
    for (int i = tid; i < HDIM * HDIM; i += 256) {
        float s = 0.0f;
#pragma unroll
        for (int w2 = 0; w2 < 8; w2++) s += red[w2 * (HDIM * HDIM) + i];
        atomicAdd(&g_gram[bh * HDIM * HDIM + i], s);
    }
}

// ---------------- softmax + fold projection: M = proj * blockdiag(attn) ----------------
__global__ void __launch_bounds__(256) attn_proj_kernel(
    const float* __restrict__ temp, const float* __restrict__ projw)
{
    const int h = blockIdx.x, b = blockIdx.y;
    __shared__ float attn[HDIM][HDIM];
    __shared__ float nq[HDIM], nk[HDIM];
    const int tid = threadIdx.x;

    if (tid < HDIM) {
        nq[tid] = fmaxf(sqrtf(g_sums[b * 2 * CIN + h * HDIM + tid]), 1e-12f);
        nk[tid] = fmaxf(sqrtf(g_sums[b * 2 * CIN + CIN + h * HDIM + tid]), 1e-12f);
    }
    __syncthreads();

    if (tid < HDIM) {
        const float t = temp[h];
        const float* gg = g_gram + ((b * NHEADS + h) * HDIM + tid) * HDIM;
        float row[HDIM];
        float mx = -1e30f;
        const float inq = 1.0f / nq[tid];
#pragma unroll
        for (int e = 0; e < HDIM; e++) {
            row[e] = gg[e] * t * inq / nk[e];
            mx = fmaxf(mx, row[e]);
        }
        float ssum = 0.0f;
#pragma unroll
        for (int e = 0; e < HDIM; e++) { row[e] = expf(row[e] - mx); ssum += row[e]; }
        const float inv = 1.0f / ssum;
#pragma unroll
        for (int e = 0; e < HDIM; e++) attn[tid][e] = row[e] * inv;
    }
    __syncthreads();

    for (int idx = tid; idx < CIN * HDIM; idx += 256) {
        const int o = idx / HDIM, e = idx % HDIM;
        float ssum = 0.0f;
#pragma unroll
        for (int d = 0; d < HDIM; d++)
            ssum = fmaf(projw[o * CIN + h * HDIM + d], attn[d][e], ssum);
        g_M[(size_t)b * CIN * CIN + o * CIN + h * HDIM + e] = ssum;
    }
}

// ---------------- launch ----------------
extern "C" void kernel_launch(void* const* d_in, const int* in_sizes, int n_in,
                              void* d_out, int out_size)
{
    const float *x = nullptr, *qkvw = nullptr, *dww = nullptr, *projw = nullptr, *temp = nullptr;
    for (int i = 0; i < n_in; i++) {
        switch (in_sizes[i]) {
            case NB * CIN * HW:   x     = (const float*)d_in[i]; break;
            case C3 * CIN:        qkvw  = (const float*)d_in[i]; break;
            case C3 * 9:          dww   = (const float*)d_in[i]; break;
            case CIN * CIN:       projw = (const float*)d_in[i]; break;
            case NHEADS:          temp  = (const float*)d_in[i]; break;
        }
    }
    float* out = (float*)d_out;

    static int configured = 0;
    if (!configured) {
        cudaFuncSetAttribute(gemm_mma_kernel<0>, cudaFuncAttributeMaxDynamicSharedMemorySize, GEMM_SMEM_BYTES);
        cudaFuncSetAttribute(gemm_mma_kernel<1>, cudaFuncAttributeMaxDynamicSharedMemorySize, GEMM_SMEM_BYTES);
        cudaFuncSetAttribute(gram_tc_kernel, cudaFuncAttributeMaxDynamicSharedMemorySize, GRAM_SMEM_BYTES);
        configured = 1;
    }

    zero_small_kernel<<<72, 256>>>();

    // qkv 1x1 conv: channel tiles fastest -> concurrent blocks share x slice in L2
    gemm_mma_kernel<0><<<dim3(3, HW / BN, NB), 256, GEMM_SMEM_BYTES>>>(x, qkvw, nullptr);

    // depthwise 3x3 (+ fused q/k sum-of-squares)
    dwconv3x3_kernel<<<dim3(NB * C3, HEI / 32), 256>>>(dww);

    // tensor-core gram (3xTF32)
    gram_tc_kernel<<<dim3(GP, NB * NHEADS), 256, GRAM_SMEM_BYTES>>>();

    // softmax + fold projection into per-batch M
    attn_proj_kernel<<<dim3(NHEADS, NB), 256>>>(temp, projw);

    // final: out = M @ v
    gemm_mma_kernel<1><<<dim3(1, HW / BN, NB), 256, GEMM_SMEM_BYTES>>>(nullptr, nullptr, out);
}